// round 11
// baseline (speedup 1.0000x reference)
#include <cuda_runtime.h>
#include <cstdint>

// Problem constants
#define BB 2
#define SS 2048
#define DD 1024
#define HH 16
#define DK 64
#define MROWS (BB * SS)   // 4096

// Scratch (static device globals — allocation-guard safe)
__device__ float g_q[MROWS * DD];
__device__ float g_k[MROWS * DD];
__device__ float g_v[MROWS * DD];
__device__ float g_o[MROWS * DD];
__device__ uint32_t g_vt[MROWS * DD];   // per-head transposed V (tf32 bits)

// ---------------------------------------------------------------------------
// Helpers
// ---------------------------------------------------------------------------
static __device__ __forceinline__ uint32_t f2tf32(float x) {
    uint32_t u;
    asm("cvt.rna.tf32.f32 %0, %1;" : "=r"(u) : "f"(x));
    return u;
}

static __device__ __forceinline__ uint32_t cvta_smem(const void* p) {
    uint32_t a;
    asm("{ .reg .u64 t; cvta.to.shared.u64 t, %1; cvt.u32.u64 %0, t; }"
        : "=r"(a) : "l"(p));
    return a;
}

static __device__ __forceinline__ void mma_tf32(float c[4], const uint32_t a[4],
                                                uint32_t b0, uint32_t b1) {
    asm volatile(
        "mma.sync.aligned.m16n8k8.row.col.f32.tf32.tf32.f32 "
        "{%0,%1,%2,%3}, {%4,%5,%6,%7}, {%8,%9}, {%0,%1,%2,%3};"
        : "+f"(c[0]), "+f"(c[1]), "+f"(c[2]), "+f"(c[3])
        : "r"(a[0]), "r"(a[1]), "r"(a[2]), "r"(a[3]), "r"(b0), "r"(b1));
}

static __device__ __forceinline__ void ldsm_x4(uint32_t r[4], uint32_t addr) {
    asm volatile("ldmatrix.sync.aligned.m8n8.x4.shared.b16 {%0,%1,%2,%3}, [%4];"
        : "=r"(r[0]), "=r"(r[1]), "=r"(r[2]), "=r"(r[3]) : "r"(addr));
}

static __device__ __forceinline__ void cp16(uint32_t dst, const void* src) {
    asm volatile("cp.async.cg.shared.global [%0], [%1], 16;"
                 :: "r"(dst), "l"(src) : "memory");
}
#define CP_COMMIT() asm volatile("cp.async.commit_group;" ::: "memory")
#define CP_WAIT0()  asm volatile("cp.async.wait_group 0;" ::: "memory")

// ---------------------------------------------------------------------------
// Fused tf32 mma.sync GEMM (R6 config): C[z] = A[z] @ W[z]^T + bias[z].
// CTA 128x128, BK=16, 128 threads (4 warps of 64x64). doRound: tf32-round C.
// ---------------------------------------------------------------------------
#define BK 16
#define APAD 20
#define GBUF (128 * APAD)

__global__ __launch_bounds__(128, 2) void gemm3_mma_kernel(
    const float* __restrict__ A0, const float* __restrict__ A1, const float* __restrict__ A2,
    const float* __restrict__ W0, const float* __restrict__ W1, const float* __restrict__ W2,
    const float* __restrict__ b0p, const float* __restrict__ b1p, const float* __restrict__ b2p,
    float* __restrict__ C0, float* __restrict__ C1, float* __restrict__ C2,
    int doRound)
{
    __shared__ uint32_t As[2][GBUF];
    __shared__ uint32_t Bs[2][GBUF];

    const int z = blockIdx.z;
    const float* A = (z == 0) ? A0 : (z == 1) ? A1 : A2;
    const float* W = (z == 0) ? W0 : (z == 1) ? W1 : W2;
    const float* bias = (z == 0) ? b0p : (z == 1) ? b1p : b2p;
    float* C = (z == 0) ? C0 : (z == 1) ? C1 : C2;

    const int tid = threadIdx.x;
    const int lane = tid & 31;
    const int wid = tid >> 5;
    const int wm = wid & 1;
    const int wn = wid >> 1;
    const int l4 = lane >> 2;
    const int lm = lane & 3;
    const int rowBase = blockIdx.y * 128;
    const int colBase = blockIdx.x * 128;

    const uint32_t asb = cvta_smem(As);
    const uint32_t bsb = cvta_smem(Bs);

    uint32_t aOff[4], bOff[4];
#pragma unroll
    for (int mt = 0; mt < 4; mt++)
        aOff[mt] = ((wm * 64 + mt * 16 + (lane & 15)) * APAD + ((lane >> 4) << 2)) * 4;
#pragma unroll
    for (int t = 0; t < 4; t++)
        bOff[t] = ((wn * 64 + t * 16 + (lane & 7) + 8 * ((lane >> 4) & 1)) * APAD
                   + 4 * ((lane >> 3) & 1)) * 4;

    float acc[4][8][4];
#pragma unroll
    for (int mt = 0; mt < 4; mt++)
#pragma unroll
        for (int nt = 0; nt < 8; nt++)
#pragma unroll
            for (int r = 0; r < 4; r++) acc[mt][nt][r] = 0.0f;

    float4 ra[4], rb[4];
    auto loadg = [&](int ic) {
        const int kOff = ic * BK;
#pragma unroll
        for (int i = 0; i < 4; i++) {
            int fi = tid + 128 * i;
            int row = fi >> 2;
            int k4 = fi & 3;
            ra[i] = *(const float4*)(A + (size_t)(rowBase + row) * DD + kOff + k4 * 4);
            rb[i] = *(const float4*)(W + (size_t)(colBase + row) * DD + kOff + k4 * 4);
        }
    };

    loadg(0);
    const int nChunks = DD / BK;

    for (int ic = 0; ic < nChunks; ic++) {
        const int buf = ic & 1;
        const uint32_t bufB = buf * (GBUF * 4);
#pragma unroll
        for (int i = 0; i < 4; i++) {
            int fi = tid + 128 * i;
            int row = fi >> 2;
            int k4 = fi & 3;
            uint32_t* da = &As[buf][row * APAD + k4 * 4];
            da[0] = f2tf32(ra[i].x); da[1] = f2tf32(ra[i].y);
            da[2] = f2tf32(ra[i].z); da[3] = f2tf32(ra[i].w);
            uint32_t* db = &Bs[buf][row * APAD + k4 * 4];
            db[0] = f2tf32(rb[i].x); db[1] = f2tf32(rb[i].y);
            db[2] = f2tf32(rb[i].z); db[3] = f2tf32(rb[i].w);
        }
        __syncthreads();

        if (ic + 1 < nChunks) loadg(ic + 1);

#pragma unroll
        for (int ks = 0; ks < 2; ks++) {
            const uint32_t kbB = ks * 32;
            uint32_t af[4][4];
#pragma unroll
            for (int mt = 0; mt < 4; mt++)
                ldsm_x4(af[mt], asb + bufB + aOff[mt] + kbB);
#pragma unroll
            for (int t = 0; t < 4; t++) {
                uint32_t bb[4];
                ldsm_x4(bb, bsb + bufB + bOff[t] + kbB);
#pragma unroll
                for (int mt = 0; mt < 4; mt++) {
                    mma_tf32(acc[mt][2 * t],     af[mt], bb[0], bb[1]);
                    mma_tf32(acc[mt][2 * t + 1], af[mt], bb[2], bb[3]);
                }
            }
        }
    }

#pragma unroll
    for (int nt = 0; nt < 8; nt++) {
        int c = colBase + wn * 64 + nt * 8 + 2 * lm;
        float2 bv = *(const float2*)(bias + c);
#pragma unroll
        for (int mt = 0; mt < 4; mt++) {
            int r = rowBase + wm * 64 + mt * 16 + l4;
            float2 o0 = make_float2(acc[mt][nt][0] + bv.x, acc[mt][nt][1] + bv.y);
            float2 o1 = make_float2(acc[mt][nt][2] + bv.x, acc[mt][nt][3] + bv.y);
            if (doRound) {
                o0.x = __uint_as_float(f2tf32(o0.x)); o0.y = __uint_as_float(f2tf32(o0.y));
                o1.x = __uint_as_float(f2tf32(o1.x)); o1.y = __uint_as_float(f2tf32(o1.y));
            }
            *(float2*)(C + (size_t)r * DD + c) = o0;
            *(float2*)(C + (size_t)(r + 8) * DD + c) = o1;
        }
    }
}

// ---------------------------------------------------------------------------
// Per-head V transpose: Vt[(b*HH+h)*DK + d][s] = V[b*SS + s][h*DK + d]
// Tiled 32x32 via smem; both sides coalesced. Data is tf32 bits (uint copy).
// ---------------------------------------------------------------------------
__global__ __launch_bounds__(256) void transpose_v_kernel(
    const uint32_t* __restrict__ vin, uint32_t* __restrict__ vt)
{
    __shared__ uint32_t ts[32][33];
    const int s0 = blockIdx.x * 32;
    const int d0 = blockIdx.y * 32;
    const int bh = blockIdx.z;
    const int b = bh >> 4, h = bh & 15;
    const uint32_t* src = vin + (size_t)b * SS * DD + h * DK;
    uint32_t* dst = vt + (size_t)bh * DK * SS;
#pragma unroll
    for (int i = threadIdx.y; i < 32; i += 8)
        ts[i][threadIdx.x] = src[(size_t)(s0 + i) * DD + d0 + threadIdx.x];
    __syncthreads();
#pragma unroll
    for (int i = threadIdx.y; i < 32; i += 8)
        dst[(size_t)(d0 + i) * SS + s0 + threadIdx.x] = ts[threadIdx.x][i];
}

// ---------------------------------------------------------------------------
// Flash attention (causal), tf32 mma.sync, cp.async K/V, pre-rounded inputs.
// 128 threads (4 warps, 16 q-rows each), 64 q-rows/CTA, 64-key tiles.
// Smem: K[2]/Vt[2] tiles 16KB each (64 rows x 16 chunks, chunk^=(row&7)) + Ps.
// ---------------------------------------------------------------------------
#define KVT 16384
#define FLASH_SMEM (4 * KVT + 16384)   // 81920 B

__global__ __launch_bounds__(128, 2) void flash_cp_kernel(
    const uint32_t* __restrict__ Qg, const uint32_t* __restrict__ Kg,
    const uint32_t* __restrict__ Vt, float* __restrict__ Og)
{
    extern __shared__ uint32_t sm[];

    const int tid = threadIdx.x;
    const int lane = tid & 31;
    const int wid = tid >> 5;
    const int l4 = lane >> 2;
    const int lm = lane & 3;

    const int qt = (gridDim.x - 1) - blockIdx.x;   // heavy tiles first
    const int h  = blockIdx.y;
    const int b  = blockIdx.z;
    const int q0 = qt * 64;

    const size_t baseQ = (size_t)b * SS * DD + (size_t)h * DK;      // Q,K rows [s][1024]
    const size_t baseV = (size_t)(b * HH + h) * DK * SS;            // Vt rows [d][2048]

    const int gr0 = q0 + wid * 16 + l4;
    const int prow = wid * 16 + l4;

    const uint32_t smb = cvta_smem(sm);
    const uint32_t psb = smb + 4 * KVT;

    // B-fragment (K and Vt) ldsm addressing: row, swizzle per t
    uint32_t rowB[4], swB[4];
#pragma unroll
    for (int t = 0; t < 4; t++) {
        uint32_t r = t * 16 + (lane & 7) + 8 * ((lane >> 4) & 1);
        rowB[t] = r * 256;
        swB[t] = r & 7;
    }
    const uint32_t cb = (lane >> 3) & 1;
    // P A-fragment addressing
    const uint32_t rowP = wid * 16 + (lane & 15);
    const uint32_t pRowOff = rowP * 256;
    const uint32_t swP = rowP & 7;
    const uint32_t ca = lane >> 4;
    // P write addressing (rows prow, prow+8)
    const uint32_t pw0 = psb + prow * 256 + (lm & 1) * 8;
    const uint32_t pw1 = psb + (prow + 8) * 256 + (lm & 1) * 8;
    const uint32_t swW0 = prow & 7;
    const uint32_t swW1 = (prow + 8) & 7;

    // Q fragments: bit-copy (already tf32-rounded)
    uint32_t qf[8][4];
#pragma unroll
    for (int ks = 0; ks < 8; ks++) {
        const uint32_t* q0p = Qg + baseQ + (size_t)gr0 * DD;
        const uint32_t* q1p = Qg + baseQ + (size_t)(gr0 + 8) * DD;
        qf[ks][0] = q0p[ks * 8 + lm];
        qf[ks][1] = q1p[ks * 8 + lm];
        qf[ks][2] = q0p[ks * 8 + lm + 4];
        qf[ks][3] = q1p[ks * 8 + lm + 4];
    }

    float oacc[8][4];
#pragma unroll
    for (int dt = 0; dt < 8; dt++)
#pragma unroll
        for (int r = 0; r < 4; r++) oacc[dt][r] = 0.0f;
    float m0 = -1e30f, m1 = -1e30f, l0 = 0.0f, l1 = 0.0f;

    // cp.async K/V tile loader: thread -> row tid>>1, 8 chunks of 16B
    const int krow = tid >> 1;
    const uint32_t kcb = (tid & 1) * 8;
    const uint32_t ksw = krow & 7;
    auto issueKV = [&](int kt, int buf) {
        const int k0 = kt * 64;
        const uint32_t kd = smb + buf * KVT + krow * 256;
        const uint32_t vd = smb + (2 + buf) * KVT + krow * 256;
        // K: rows advance with k0 (row-major [s][1024])
        const uint32_t* ksrc = Kg + baseQ + (size_t)(k0 + krow) * DD;
        // Vt: columns advance with k0 (row-major [d][2048])
        const uint32_t* vsrc = Vt + baseV + (size_t)krow * SS + k0;
#pragma unroll
        for (int j = 0; j < 8; j++) {
            uint32_t c = kcb + j;
            uint32_t ph = ((c ^ ksw) << 4);
            cp16(kd + ph, ksrc + c * 4);
            cp16(vd + ph, vsrc + c * 4);
        }
        CP_COMMIT();
    };

    issueKV(0, 0);
    CP_WAIT0();
    __syncthreads();

    const int nkt = qt + 1;
    for (int kt = 0; kt < nkt; kt++) {
        const int k0 = kt * 64;
        const int buf = kt & 1;
        const uint32_t kBuf = smb + buf * KVT;
        const uint32_t vBuf = smb + (2 + buf) * KVT;

        // S = Q @ K^T
        float sf[8][4];
#pragma unroll
        for (int nt = 0; nt < 8; nt++)
#pragma unroll
            for (int r = 0; r < 4; r++) sf[nt][r] = 0.0f;

#pragma unroll
        for (int ks = 0; ks < 8; ks++) {
            const uint32_t ck = cb + ks * 2;
#pragma unroll
            for (int t = 0; t < 4; t++) {
                uint32_t bb[4];
                ldsm_x4(bb, kBuf + rowB[t] + ((ck ^ swB[t]) << 4));
                mma_tf32(sf[2 * t],     qf[ks], bb[0], bb[1]);
                mma_tf32(sf[2 * t + 1], qf[ks], bb[2], bb[3]);
            }
        }

        if (kt + 1 < nkt) issueKV(kt + 1, buf ^ 1);   // fill other buffer

        const float scale = 0.125f;
#pragma unroll
        for (int nt = 0; nt < 8; nt++)
#pragma unroll
            for (int r = 0; r < 4; r++) sf[nt][r] *= scale;

        if (k0 + 63 > q0 + wid * 16) {
#pragma unroll
            for (int nt = 0; nt < 8; nt++) {
                int c = k0 + nt * 8 + 2 * lm;
                if (c     > gr0)     sf[nt][0] = -1e30f;
                if (c + 1 > gr0)     sf[nt][1] = -1e30f;
                if (c     > gr0 + 8) sf[nt][2] = -1e30f;
                if (c + 1 > gr0 + 8) sf[nt][3] = -1e30f;
            }
        }

        // online softmax
        float rm0 = -1e30f, rm1 = -1e30f;
#pragma unroll
        for (int nt = 0; nt < 8; nt++) {
            rm0 = fmaxf(rm0, fmaxf(sf[nt][0], sf[nt][1]));
            rm1 = fmaxf(rm1, fmaxf(sf[nt][2], sf[nt][3]));
        }
#pragma unroll
        for (int off = 1; off <= 2; off <<= 1) {
            rm0 = fmaxf(rm0, __shfl_xor_sync(0xffffffffu, rm0, off));
            rm1 = fmaxf(rm1, __shfl_xor_sync(0xffffffffu, rm1, off));
        }
        float nm0 = fmaxf(m0, rm0), nm1 = fmaxf(m1, rm1);
        float a0 = __expf(m0 - nm0), a1 = __expf(m1 - nm1);
        float rs0 = 0.0f, rs1 = 0.0f;
#pragma unroll
        for (int nt = 0; nt < 8; nt++) {
            sf[nt][0] = __expf(sf[nt][0] - nm0);
            sf[nt][1] = __expf(sf[nt][1] - nm0);
            sf[nt][2] = __expf(sf[nt][2] - nm1);
            sf[nt][3] = __expf(sf[nt][3] - nm1);
            rs0 += sf[nt][0] + sf[nt][1];
            rs1 += sf[nt][2] + sf[nt][3];
        }
#pragma unroll
        for (int off = 1; off <= 2; off <<= 1) {
            rs0 += __shfl_xor_sync(0xffffffffu, rs0, off);
            rs1 += __shfl_xor_sync(0xffffffffu, rs1, off);
        }
        l0 = l0 * a0 + rs0;  m0 = nm0;
        l1 = l1 * a1 + rs1;  m1 = nm1;
#pragma unroll
        for (int dt = 0; dt < 8; dt++) {
            oacc[dt][0] *= a0; oacc[dt][1] *= a0;
            oacc[dt][2] *= a1; oacc[dt][3] *= a1;
        }

        // P -> smem (tf32 bits), swizzled, warp-private rows
#pragma unroll
        for (int nt = 0; nt < 8; nt++) {
            uint32_t chunk = nt * 2 + (lm >> 1);
            uint2 p0 = make_uint2(f2tf32(sf[nt][0]), f2tf32(sf[nt][1]));
            uint2 p1 = make_uint2(f2tf32(sf[nt][2]), f2tf32(sf[nt][3]));
            asm volatile("st.shared.v2.b32 [%0], {%1,%2};"
                :: "r"(pw0 + ((chunk ^ swW0) << 4)), "r"(p0.x), "r"(p0.y) : "memory");
            asm volatile("st.shared.v2.b32 [%0], {%1,%2};"
                :: "r"(pw1 + ((chunk ^ swW1) << 4)), "r"(p1.x), "r"(p1.y) : "memory");
        }
        __syncwarp();

        // O += P @ V
#pragma unroll
        for (int ks = 0; ks < 8; ks++) {
            uint32_t af[4];
            ldsm_x4(af, psb + pRowOff + (((ca + ks * 2) ^ swP) << 4));
            const uint32_t ck = cb + ks * 2;
#pragma unroll
            for (int t = 0; t < 4; t++) {
                uint32_t bb[4];
                ldsm_x4(bb, vBuf + rowB[t] + ((ck ^ swB[t]) << 4));
                mma_tf32(oacc[2 * t],     af, bb[0], bb[1]);
                mma_tf32(oacc[2 * t + 1], af, bb[2], bb[3]);
            }
        }

        if (kt + 1 < nkt) {
            CP_WAIT0();        // next tile's cp.async complete
            __syncthreads();
        }
    }

    float inv0 = 1.0f / l0, inv1 = 1.0f / l1;
#pragma unroll
    for (int dt = 0; dt < 8; dt++) {
        int d = dt * 8 + 2 * lm;
        float2 o0 = make_float2(oacc[dt][0] * inv0, oacc[dt][1] * inv0);
        float2 o1 = make_float2(oacc[dt][2] * inv1, oacc[dt][3] * inv1);
        *(float2*)(Og + baseQ + (size_t)gr0 * DD + d) = o0;
        *(float2*)(Og + baseQ + (size_t)(gr0 + 8) * DD + d) = o1;
    }
}

// ---------------------------------------------------------------------------
// Launch
// ---------------------------------------------------------------------------
extern "C" void kernel_launch(void* const* d_in, const int* in_sizes, int n_in,
                              void* d_out, int out_size)
{
    const float* query = (const float*)d_in[0];
    const float* key   = (const float*)d_in[1];
    const float* value = (const float*)d_in[2];
    const float* wq = (const float*)d_in[3];
    const float* bq = (const float*)d_in[4];
    const float* wk = (const float*)d_in[5];
    const float* bk = (const float*)d_in[6];
    const float* wv = (const float*)d_in[7];
    const float* bv = (const float*)d_in[8];
    const float* wo = (const float*)d_in[9];
    const float* bo = (const float*)d_in[10];
    float* out = (float*)d_out;

    float *q_s, *k_s, *v_s, *o_s;
    uint32_t* vt;
    cudaGetSymbolAddress((void**)&q_s, g_q);
    cudaGetSymbolAddress((void**)&k_s, g_k);
    cudaGetSymbolAddress((void**)&v_s, g_v);
    cudaGetSymbolAddress((void**)&o_s, g_o);
    cudaGetSymbolAddress((void**)&vt, g_vt);

    cudaFuncSetAttribute(flash_cp_kernel,
                         cudaFuncAttributeMaxDynamicSharedMemorySize, FLASH_SMEM);

    // 1. fused q/k/v projections, outputs tf32-rounded
    dim3 gproj3(DD / 128, MROWS / 128, 3);
    gemm3_mma_kernel<<<gproj3, 128>>>(query, key, value, wq, wk, wv,
                                      bq, bk, bv, q_s, k_s, v_s, 1);

    // 2. per-head V transpose (tf32 bits)
    dim3 gtr(SS / 32, DK / 32, BB * HH);
    transpose_v_kernel<<<gtr, dim3(32, 8)>>>((const uint32_t*)v_s, vt);

    // 3. flash attention
    dim3 gattn(SS / 64, HH, BB);   // (32, 16, 2)
    flash_cp_kernel<<<gattn, 128, FLASH_SMEM>>>(
        (const uint32_t*)q_s, (const uint32_t*)k_s, vt, o_s);

    // 4. output projection (full fp32)
    dim3 gproj1(DD / 128, MROWS / 128, 1);
    gemm3_mma_kernel<<<gproj1, 128>>>(o_s, o_s, o_s, wo, wo, wo,
                                      bo, bo, bo, out, out, out, 0);
}

// round 12
// speedup vs baseline: 1.0855x; 1.0855x over previous
#include <cuda_runtime.h>
#include <cstdint>

// Problem constants
#define BB 2
#define SS 2048
#define DD 1024
#define HH 16
#define DK 64
#define MROWS (BB * SS)   // 4096

// Scratch (static device globals — allocation-guard safe)
__device__ float g_q[MROWS * DD];
__device__ float g_k[MROWS * DD];
__device__ float g_v[MROWS * DD];
__device__ float g_o[MROWS * DD];

// ---------------------------------------------------------------------------
// Helpers
// ---------------------------------------------------------------------------
static __device__ __forceinline__ uint32_t f2tf32(float x) {
    uint32_t u;
    asm("cvt.rna.tf32.f32 %0, %1;" : "=r"(u) : "f"(x));
    return u;
}

static __device__ __forceinline__ float ex2f(float x) {
    float r;
    asm("ex2.approx.f32 %0, %1;" : "=f"(r) : "f"(x));
    return r;
}

static __device__ __forceinline__ uint32_t cvta_smem(const void* p) {
    uint32_t a;
    asm("{ .reg .u64 t; cvta.to.shared.u64 t, %1; cvt.u32.u64 %0, t; }"
        : "=r"(a) : "l"(p));
    return a;
}

static __device__ __forceinline__ void mma_tf32(float c[4], const uint32_t a[4],
                                                uint32_t b0, uint32_t b1) {
    asm volatile(
        "mma.sync.aligned.m16n8k8.row.col.f32.tf32.tf32.f32 "
        "{%0,%1,%2,%3}, {%4,%5,%6,%7}, {%8,%9}, {%0,%1,%2,%3};"
        : "+f"(c[0]), "+f"(c[1]), "+f"(c[2]), "+f"(c[3])
        : "r"(a[0]), "r"(a[1]), "r"(a[2]), "r"(a[3]), "r"(b0), "r"(b1));
}

static __device__ __forceinline__ void ldsm_x4(uint32_t r[4], uint32_t addr) {
    asm volatile("ldmatrix.sync.aligned.m8n8.x4.shared.b16 {%0,%1,%2,%3}, [%4];"
        : "=r"(r[0]), "=r"(r[1]), "=r"(r[2]), "=r"(r[3]) : "r"(addr));
}

// ---------------------------------------------------------------------------
// Fused tf32 mma.sync GEMM (R6 config): C[z] = A[z] @ W[z]^T + bias[z].
// CTA 128x128, BK=16, 128 threads (4 warps of 64x64). doRound: tf32-round C.
// ---------------------------------------------------------------------------
#define BK 16
#define APAD 20
#define GBUF (128 * APAD)

__global__ __launch_bounds__(128, 2) void gemm3_mma_kernel(
    const float* __restrict__ A0, const float* __restrict__ A1, const float* __restrict__ A2,
    const float* __restrict__ W0, const float* __restrict__ W1, const float* __restrict__ W2,
    const float* __restrict__ b0p, const float* __restrict__ b1p, const float* __restrict__ b2p,
    float* __restrict__ C0, float* __restrict__ C1, float* __restrict__ C2,
    int doRound)
{
    __shared__ uint32_t As[2][GBUF];
    __shared__ uint32_t Bs[2][GBUF];

    const int z = blockIdx.z;
    const float* A = (z == 0) ? A0 : (z == 1) ? A1 : A2;
    const float* W = (z == 0) ? W0 : (z == 1) ? W1 : W2;
    const float* bias = (z == 0) ? b0p : (z == 1) ? b1p : b2p;
    float* C = (z == 0) ? C0 : (z == 1) ? C1 : C2;

    const int tid = threadIdx.x;
    const int lane = tid & 31;
    const int wid = tid >> 5;
    const int wm = wid & 1;
    const int wn = wid >> 1;
    const int l4 = lane >> 2;
    const int lm = lane & 3;
    const int rowBase = blockIdx.y * 128;
    const int colBase = blockIdx.x * 128;

    const uint32_t asb = cvta_smem(As);
    const uint32_t bsb = cvta_smem(Bs);

    uint32_t aOff[4], bOff[4];
#pragma unroll
    for (int mt = 0; mt < 4; mt++)
        aOff[mt] = ((wm * 64 + mt * 16 + (lane & 15)) * APAD + ((lane >> 4) << 2)) * 4;
#pragma unroll
    for (int t = 0; t < 4; t++)
        bOff[t] = ((wn * 64 + t * 16 + (lane & 7) + 8 * ((lane >> 4) & 1)) * APAD
                   + 4 * ((lane >> 3) & 1)) * 4;

    float acc[4][8][4];
#pragma unroll
    for (int mt = 0; mt < 4; mt++)
#pragma unroll
        for (int nt = 0; nt < 8; nt++)
#pragma unroll
            for (int r = 0; r < 4; r++) acc[mt][nt][r] = 0.0f;

    float4 ra[4], rb[4];
    auto loadg = [&](int ic) {
        const int kOff = ic * BK;
#pragma unroll
        for (int i = 0; i < 4; i++) {
            int fi = tid + 128 * i;
            int row = fi >> 2;
            int k4 = fi & 3;
            ra[i] = *(const float4*)(A + (size_t)(rowBase + row) * DD + kOff + k4 * 4);
            rb[i] = *(const float4*)(W + (size_t)(colBase + row) * DD + kOff + k4 * 4);
        }
    };

    loadg(0);
    const int nChunks = DD / BK;

    for (int ic = 0; ic < nChunks; ic++) {
        const int buf = ic & 1;
        const uint32_t bufB = buf * (GBUF * 4);
#pragma unroll
        for (int i = 0; i < 4; i++) {
            int fi = tid + 128 * i;
            int row = fi >> 2;
            int k4 = fi & 3;
            uint32_t* da = &As[buf][row * APAD + k4 * 4];
            da[0] = f2tf32(ra[i].x); da[1] = f2tf32(ra[i].y);
            da[2] = f2tf32(ra[i].z); da[3] = f2tf32(ra[i].w);
            uint32_t* db = &Bs[buf][row * APAD + k4 * 4];
            db[0] = f2tf32(rb[i].x); db[1] = f2tf32(rb[i].y);
            db[2] = f2tf32(rb[i].z); db[3] = f2tf32(rb[i].w);
        }
        __syncthreads();

        if (ic + 1 < nChunks) loadg(ic + 1);

#pragma unroll
        for (int ks = 0; ks < 2; ks++) {
            const uint32_t kbB = ks * 32;
            uint32_t af[4][4];
#pragma unroll
            for (int mt = 0; mt < 4; mt++)
                ldsm_x4(af[mt], asb + bufB + aOff[mt] + kbB);
#pragma unroll
            for (int t = 0; t < 4; t++) {
                uint32_t bb[4];
                ldsm_x4(bb, bsb + bufB + bOff[t] + kbB);
#pragma unroll
                for (int mt = 0; mt < 4; mt++) {
                    mma_tf32(acc[mt][2 * t],     af[mt], bb[0], bb[1]);
                    mma_tf32(acc[mt][2 * t + 1], af[mt], bb[2], bb[3]);
                }
            }
        }
    }

#pragma unroll
    for (int nt = 0; nt < 8; nt++) {
        int c = colBase + wn * 64 + nt * 8 + 2 * lm;
        float2 bv = *(const float2*)(bias + c);
#pragma unroll
        for (int mt = 0; mt < 4; mt++) {
            int r = rowBase + wm * 64 + mt * 16 + l4;
            float2 o0 = make_float2(acc[mt][nt][0] + bv.x, acc[mt][nt][1] + bv.y);
            float2 o1 = make_float2(acc[mt][nt][2] + bv.x, acc[mt][nt][3] + bv.y);
            if (doRound) {
                o0.x = __uint_as_float(f2tf32(o0.x)); o0.y = __uint_as_float(f2tf32(o0.y));
                o1.x = __uint_as_float(f2tf32(o1.x)); o1.y = __uint_as_float(f2tf32(o1.y));
            }
            *(float2*)(C + (size_t)r * DD + c) = o0;
            *(float2*)(C + (size_t)(r + 8) * DD + c) = o1;
        }
    }
}

// ---------------------------------------------------------------------------
// Flash attention (causal), tf32 mma.sync, ldmatrix frags.
// R9 structure: 128 threads (4 warps, 16 q-rows each), 64 q-rows/CTA,
// 64-key tiles, double-buffered K/V smem, single sync per tile.
// NEW: inputs pre-rounded tf32 (bit-copy staging), log2-domain softmax with
// scale*log2e folded into Q once per CTA.
// ---------------------------------------------------------------------------
#define FS 68
#define FLASH_SMEM ((4 * 64 + 64) * FS * 4)   // 87040 B
#define SCALE_LOG2E 0.180336880f              // 0.125 * log2(e)

__global__ __launch_bounds__(128, 2) void flash_mma_kernel(
    const float* __restrict__ Qg, const float* __restrict__ Kg,
    const float* __restrict__ Vg, float* __restrict__ Og)
{
    extern __shared__ uint32_t sm[];
    uint32_t* Ps = sm + 4 * 64 * FS;   // [64][FS]

    const int tid = threadIdx.x;
    const int lane = tid & 31;
    const int wid = tid >> 5;          // 0..3
    const int l4 = lane >> 2;
    const int lm = lane & 3;

    const int qt = (gridDim.x - 1) - blockIdx.x;   // heavy tiles first
    const int h  = blockIdx.y;
    const int b  = blockIdx.z;
    const int q0 = qt * 64;

    const size_t base = (size_t)b * SS * DD + (size_t)h * DK;

    const int gr0 = q0 + wid * 16 + l4;
    const int prow = wid * 16 + l4;

    const uint32_t smb = cvta_smem(sm);
    const uint32_t psb = smb + 4 * 64 * FS * 4;

    uint32_t kvOff[4];
#pragma unroll
    for (int t = 0; t < 4; t++)
        kvOff[t] = ((t * 16 + (lane & 7) + 8 * ((lane >> 4) & 1)) * FS
                    + 4 * ((lane >> 3) & 1)) * 4;
    const uint32_t pOff = ((wid * 16 + (lane & 15)) * FS + ((lane >> 4) << 2)) * 4;

    // Q fragments: bit-copy (pre-rounded), premultiplied by scale*log2e,
    // re-rounded rna to tf32. Amortized once per CTA.
    uint32_t qf[8][4];
#pragma unroll
    for (int ks = 0; ks < 8; ks++) {
        const float* q0p = Qg + base + (size_t)gr0 * DD;
        const float* q1p = Qg + base + (size_t)(gr0 + 8) * DD;
        qf[ks][0] = f2tf32(q0p[ks * 8 + lm]     * SCALE_LOG2E);
        qf[ks][1] = f2tf32(q1p[ks * 8 + lm]     * SCALE_LOG2E);
        qf[ks][2] = f2tf32(q0p[ks * 8 + lm + 4] * SCALE_LOG2E);
        qf[ks][3] = f2tf32(q1p[ks * 8 + lm + 4] * SCALE_LOG2E);
    }

    float oacc[8][4];
#pragma unroll
    for (int dt = 0; dt < 8; dt++)
#pragma unroll
        for (int r = 0; r < 4; r++) oacc[dt][r] = 0.0f;
    float m0 = -1e30f, m1 = -1e30f, l0 = 0.0f, l1 = 0.0f;

    // K/V tile register prefetch (bit copies — data already tf32)
    uint4 kr[8];
    uint32_t vr[32];
    auto load_kv = [&](int kt) {
        const int k0 = kt * 64;
        const uint32_t* Ku = (const uint32_t*)Kg;
        const uint32_t* Vu = (const uint32_t*)Vg;
#pragma unroll
        for (int i = 0; i < 8; i++) {
            int fi = tid + 128 * i;
            int row = fi >> 4;
            int c4 = (fi & 15) * 4;
            kr[i] = *(const uint4*)(Ku + base + (size_t)(k0 + row) * DD + c4);
        }
#pragma unroll
        for (int i = 0; i < 32; i++) {
            int fi = tid + 128 * i;
            int row = fi >> 6;
            int d = fi & 63;
            vr[i] = Vu[base + (size_t)(k0 + row) * DD + d];
        }
    };
    auto store_kv = [&](int buf) {
        uint32_t* Ks = sm + buf * 64 * FS;
        uint32_t* Vt = sm + (2 + buf) * 64 * FS;
#pragma unroll
        for (int i = 0; i < 8; i++) {
            int fi = tid + 128 * i;
            int row = fi >> 4;
            int c4 = (fi & 15) * 4;
            uint32_t* dst = Ks + row * FS + c4;
            dst[0] = kr[i].x; dst[1] = kr[i].y;
            dst[2] = kr[i].z; dst[3] = kr[i].w;
        }
#pragma unroll
        for (int i = 0; i < 32; i++) {
            int fi = tid + 128 * i;
            int row = fi >> 6;
            int d = fi & 63;
            Vt[d * FS + row] = vr[i];
        }
    };

    load_kv(0);
    store_kv(0);
    __syncthreads();

    const int nkt = qt + 1;
    for (int kt = 0; kt < nkt; kt++) {
        const int k0 = kt * 64;
        const int buf = kt & 1;
        const uint32_t ksBuf = smb + buf * 64 * FS * 4;
        const uint32_t vtBuf = smb + (2 + buf) * 64 * FS * 4;

        // S = (Q*scale*log2e) @ K^T   (log2-domain scores)
        float sf[8][4];
#pragma unroll
        for (int nt = 0; nt < 8; nt++)
#pragma unroll
            for (int r = 0; r < 4; r++) sf[nt][r] = 0.0f;

#pragma unroll
        for (int ks = 0; ks < 8; ks++) {
            const uint32_t kbB = ks * 32;
#pragma unroll
            for (int t = 0; t < 4; t++) {
                uint32_t bb[4];
                ldsm_x4(bb, ksBuf + kvOff[t] + kbB);
                mma_tf32(sf[2 * t],     qf[ks], bb[0], bb[1]);
                mma_tf32(sf[2 * t + 1], qf[ks], bb[2], bb[3]);
            }
        }

        if (kt + 1 < nkt) load_kv(kt + 1);   // hide LDG under softmax+PV

        if (k0 + 63 > q0 + wid * 16) {
#pragma unroll
            for (int nt = 0; nt < 8; nt++) {
                int c = k0 + nt * 8 + 2 * lm;
                if (c     > gr0)     sf[nt][0] = -1e30f;
                if (c + 1 > gr0)     sf[nt][1] = -1e30f;
                if (c     > gr0 + 8) sf[nt][2] = -1e30f;
                if (c + 1 > gr0 + 8) sf[nt][3] = -1e30f;
            }
        }

        // online softmax in log2 domain
        float rm0 = -1e30f, rm1 = -1e30f;
#pragma unroll
        for (int nt = 0; nt < 8; nt++) {
            rm0 = fmaxf(rm0, fmaxf(sf[nt][0], sf[nt][1]));
            rm1 = fmaxf(rm1, fmaxf(sf[nt][2], sf[nt][3]));
        }
#pragma unroll
        for (int off = 1; off <= 2; off <<= 1) {
            rm0 = fmaxf(rm0, __shfl_xor_sync(0xffffffffu, rm0, off));
            rm1 = fmaxf(rm1, __shfl_xor_sync(0xffffffffu, rm1, off));
        }
        float nm0 = fmaxf(m0, rm0), nm1 = fmaxf(m1, rm1);
        float a0 = ex2f(m0 - nm0), a1 = ex2f(m1 - nm1);
        float rs0 = 0.0f, rs1 = 0.0f;
#pragma unroll
        for (int nt = 0; nt < 8; nt++) {
            sf[nt][0] = ex2f(sf[nt][0] - nm0);
            sf[nt][1] = ex2f(sf[nt][1] - nm0);
            sf[nt][2] = ex2f(sf[nt][2] - nm1);
            sf[nt][3] = ex2f(sf[nt][3] - nm1);
            rs0 += sf[nt][0] + sf[nt][1];
            rs1 += sf[nt][2] + sf[nt][3];
        }
#pragma unroll
        for (int off = 1; off <= 2; off <<= 1) {
            rs0 += __shfl_xor_sync(0xffffffffu, rs0, off);
            rs1 += __shfl_xor_sync(0xffffffffu, rs1, off);
        }
        l0 = l0 * a0 + rs0;  m0 = nm0;
        l1 = l1 * a1 + rs1;  m1 = nm1;
#pragma unroll
        for (int dt = 0; dt < 8; dt++) {
            oacc[dt][0] *= a0; oacc[dt][1] *= a0;
            oacc[dt][2] *= a1; oacc[dt][3] *= a1;
        }

        // P -> smem (tf32), warp-private rows
#pragma unroll
        for (int nt = 0; nt < 8; nt++) {
            int c = nt * 8 + 2 * lm;
            uint32_t p0 = f2tf32(sf[nt][0]), p1 = f2tf32(sf[nt][1]);
            uint32_t p2 = f2tf32(sf[nt][2]), p3 = f2tf32(sf[nt][3]);
            *(uint2*)&Ps[prow * FS + c]       = make_uint2(p0, p1);
            *(uint2*)&Ps[(prow + 8) * FS + c] = make_uint2(p2, p3);
        }
        __syncwarp();

        // O += P @ V
#pragma unroll
        for (int ks = 0; ks < 8; ks++) {
            const uint32_t kbB = ks * 32;
            uint32_t af[4];
            ldsm_x4(af, psb + pOff + kbB);
#pragma unroll
            for (int t = 0; t < 4; t++) {
                uint32_t bb[4];
                ldsm_x4(bb, vtBuf + kvOff[t] + kbB);
                mma_tf32(oacc[2 * t],     af, bb[0], bb[1]);
                mma_tf32(oacc[2 * t + 1], af, bb[2], bb[3]);
            }
        }

        if (kt + 1 < nkt) {
            store_kv(buf ^ 1);
            __syncthreads();   // single sync per tile
        }
    }

    float inv0 = 1.0f / l0, inv1 = 1.0f / l1;
#pragma unroll
    for (int dt = 0; dt < 8; dt++) {
        int d = dt * 8 + 2 * lm;
        float2 o0 = make_float2(oacc[dt][0] * inv0, oacc[dt][1] * inv0);
        float2 o1 = make_float2(oacc[dt][2] * inv1, oacc[dt][3] * inv1);
        *(float2*)(Og + base + (size_t)gr0 * DD + d) = o0;
        *(float2*)(Og + base + (size_t)(gr0 + 8) * DD + d) = o1;
    }
}

// ---------------------------------------------------------------------------
// Launch
// ---------------------------------------------------------------------------
extern "C" void kernel_launch(void* const* d_in, const int* in_sizes, int n_in,
                              void* d_out, int out_size)
{
    const float* query = (const float*)d_in[0];
    const float* key   = (const float*)d_in[1];
    const float* value = (const float*)d_in[2];
    const float* wq = (const float*)d_in[3];
    const float* bq = (const float*)d_in[4];
    const float* wk = (const float*)d_in[5];
    const float* bk = (const float*)d_in[6];
    const float* wv = (const float*)d_in[7];
    const float* bv = (const float*)d_in[8];
    const float* wo = (const float*)d_in[9];
    const float* bo = (const float*)d_in[10];
    float* out = (float*)d_out;

    float *q_s, *k_s, *v_s, *o_s;
    cudaGetSymbolAddress((void**)&q_s, g_q);
    cudaGetSymbolAddress((void**)&k_s, g_k);
    cudaGetSymbolAddress((void**)&v_s, g_v);
    cudaGetSymbolAddress((void**)&o_s, g_o);

    cudaFuncSetAttribute(flash_mma_kernel,
                         cudaFuncAttributeMaxDynamicSharedMemorySize, FLASH_SMEM);

    // 1. fused q/k/v projections (outputs tf32-rounded)
    dim3 gproj3(DD / 128, MROWS / 128, 3);
    gemm3_mma_kernel<<<gproj3, 128>>>(query, key, value, wq, wk, wv,
                                      bq, bk, bv, q_s, k_s, v_s, 1);

    // 2. flash attention: 64 q-rows per CTA, 2 CTAs/SM
    dim3 gattn(SS / 64, HH, BB);   // (32, 16, 2) = 1024 CTAs
    flash_mma_kernel<<<gattn, 128, FLASH_SMEM>>>(q_s, k_s, v_s, o_s);

    // 3. output projection (full fp32 output)
    dim3 gproj1(DD / 128, MROWS / 128, 1);
    gemm3_mma_kernel<<<gproj1, 128>>>(o_s, o_s, o_s, wo, wo, wo,
                                      bo, bo, bo, out, out, out, 0);
}